// round 15
// baseline (speedup 1.0000x reference)
#include <cuda_runtime.h>
#include <cuda_bf16.h>
#include <cstdint>

// ---------------- problem constants ----------------
#define NN 2048
#define EMB 768
#define HH 8
#define DD 96
// SCALE*log2(e) = (1/sqrt(96)) * 1.4426950408889634
#define K_EXP2 0.14724447f

// ---------------- device scratch (no allocs allowed) ----------------
__device__ __align__(16) float g_Wh[NN * EMB];
__device__ __align__(16) float g_skip[NN * EMB];
__device__ __align__(16) float g_s1[NN * HH];
__device__ __align__(16) float g_s2[NN * HH];
__device__ int   g_glist[NN];
__device__ int   g_gstart[33];

// bf16 hi/lo split operands
__device__ __align__(16) __nv_bfloat16 g_ehi[NN * EMB];
__device__ __align__(16) __nv_bfloat16 g_elo[NN * EMB];
__device__ __align__(16) __nv_bfloat16 g_wwhi[EMB * EMB];
__device__ __align__(16) __nv_bfloat16 g_wwlo[EMB * EMB];
__device__ __align__(16) __nv_bfloat16 g_skhi[EMB * EMB];
__device__ __align__(16) __nv_bfloat16 g_sklo[EMB * EMB];
__device__ __align__(16) __nv_bfloat16 g_pjhi[EMB * EMB];
__device__ __align__(16) __nv_bfloat16 g_pjlo[EMB * EMB];
__device__ __align__(16) __nv_bfloat16 g_athi[NN * EMB];
__device__ __align__(16) __nv_bfloat16 g_atlo[NN * EMB];

// ---------------- low-level helpers ----------------
__device__ __forceinline__ uint32_t smem_to_u32(const void* p) {
    uint32_t a;
    asm("{ .reg .u64 t; cvta.to.shared.u64 t, %1; cvt.u32.u64 %0, t; }" : "=r"(a) : "l"(p));
    return a;
}
__device__ __forceinline__ void cp_async16(uint32_t dst, const void* src) {
    asm volatile("cp.async.cg.shared.global [%0], [%1], 16;" :: "r"(dst), "l"(src));
}
#define CP_COMMIT() asm volatile("cp.async.commit_group;")
#define CP_WAIT(n)  asm volatile("cp.async.wait_group %0;" :: "n"(n))

__device__ __forceinline__ void ldsm_x4(uint32_t* r, uint32_t addr) {
    asm volatile("ldmatrix.sync.aligned.m8n8.x4.shared.b16 {%0,%1,%2,%3}, [%4];"
                 : "=r"(r[0]), "=r"(r[1]), "=r"(r[2]), "=r"(r[3]) : "r"(addr));
}
__device__ __forceinline__ void mma16816(float* d, const uint32_t* a, uint32_t b0, uint32_t b1) {
    asm volatile(
        "mma.sync.aligned.m16n8k16.row.col.f32.bf16.bf16.f32 "
        "{%0,%1,%2,%3}, {%4,%5,%6,%7}, {%8,%9}, {%0,%1,%2,%3};"
        : "+f"(d[0]), "+f"(d[1]), "+f"(d[2]), "+f"(d[3])
        : "r"(a[0]), "r"(a[1]), "r"(a[2]), "r"(a[3]), "r"(b0), "r"(b1));
}
__device__ __forceinline__ float ex2f(float x) {
    float y;
    asm("ex2.approx.ftz.f32 %0, %1;" : "=f"(y) : "f"(x));
    return y;
}
__device__ __forceinline__ void split_bf16(float v, __nv_bfloat16& hi, __nv_bfloat16& lo) {
    hi = __float2bfloat16(v);
    lo = __float2bfloat16(v - __bfloat162float(hi));
}
__device__ __forceinline__ uint32_t pack2bf(__nv_bfloat16 a, __nv_bfloat16 b) {
    return (uint32_t)__bfloat16_as_ushort(a) | ((uint32_t)__bfloat16_as_ushort(b) << 16);
}
// swizzled byte offset inside a (rows x 32 bf16) tile: row stride 64B, 16B chunks
__device__ __forceinline__ uint32_t sw_off(uint32_t r, uint32_t chunk) {
    return r * 64u + ((chunk ^ ((r >> 1) & 3u)) << 4);
}

// ---------------------------------------------------------------------------
// fused prep: blocks [0,1536) pack e -> bf16 hi/lo; [1536, 3264) split weights
// ---------------------------------------------------------------------------
#define WQ (EMB * EMB / 4)   // 147456 float4 units per matrix
__global__ void fused_prep_kernel(const float* __restrict__ eh,
                                  const float* __restrict__ er,
                                  const float* __restrict__ et,
                                  const float* __restrict__ w0,
                                  const float* __restrict__ w1,
                                  const float* __restrict__ w2) {
    int bid = blockIdx.x;
    const float* src;
    __nv_bfloat16 *hi, *lo;
    int ridx;
    if (bid < 1536) {
        int idx4 = bid * 256 + threadIdx.x;      // < 2048*192
        int row = idx4 / 192;
        int c4 = idx4 - row * 192;
        if (c4 < 64)       src = eh + row * 256 + c4 * 4;
        else if (c4 < 128) src = er + row * 256 + (c4 - 64) * 4;
        else               src = et + row * 256 + (c4 - 128) * 4;
        hi = g_ehi; lo = g_elo; ridx = idx4;
    } else {
        int idx4 = (bid - 1536) * 256 + threadIdx.x;   // < 3*WQ
        int r;
        if (idx4 < WQ)          { src = w0; hi = g_wwhi; lo = g_wwlo; r = idx4; }
        else if (idx4 < 2 * WQ) { src = w1; hi = g_skhi; lo = g_sklo; r = idx4 - WQ; }
        else                    { src = w2; hi = g_pjhi; lo = g_pjlo; r = idx4 - 2 * WQ; }
        src = src + (size_t)r * 4; ridx = r;
    }
    float4 v = *reinterpret_cast<const float4*>(src);
    __nv_bfloat16 h0, l0, h1, l1, h2, l2, h3, l3;
    split_bf16(v.x, h0, l0); split_bf16(v.y, h1, l1);
    split_bf16(v.z, h2, l2); split_bf16(v.w, h3, l3);
    uint2 hv, lv;
    hv.x = pack2bf(h0, h1); hv.y = pack2bf(h2, h3);
    lv.x = pack2bf(l0, l1); lv.y = pack2bf(l2, l3);
    *reinterpret_cast<uint2*>(hi + (size_t)ridx * 4) = hv;
    *reinterpret_cast<uint2*>(lo + (size_t)ridx * 4) = lv;
}

// ---------------------------------------------------------------------------
// group lists via warp-ballot compaction + zero s1/s2 accumulators
// ---------------------------------------------------------------------------
__global__ void build_groups_kernel(const int* __restrict__ h_id) {
    __shared__ int hs[NN];
    __shared__ int st[33];
    int tid = threadIdx.x;
    for (int i = tid; i < NN * HH; i += 1024) { g_s1[i] = 0.f; g_s2[i] = 0.f; }
    hs[tid] = h_id[tid];
    hs[tid + 1024] = h_id[tid + 1024];
    __syncthreads();
    int w = tid >> 5, l = tid & 31;
    int cnt = 0;
    for (int base = 0; base < NN; base += 32) {
        unsigned m = __ballot_sync(0xFFFFFFFFu, hs[base + l] == w);
        cnt += __popc(m);
    }
    if (l == 0) st[w + 1] = cnt;
    __syncthreads();
    if (tid == 0) {
        st[0] = 0;
        for (int g = 1; g <= 32; g++) st[g] += st[g - 1];
    }
    __syncthreads();
    if (tid < 33) g_gstart[tid] = st[tid];
    int pos = st[w];
    for (int base = 0; base < NN; base += 32) {
        int j = base + l;
        bool hit = (hs[j] == w);
        unsigned m = __ballot_sync(0xFFFFFFFFu, hit);
        if (hit) g_glist[pos + __popc(m & ((1u << l) - 1u))] = j;
        pos += __popc(m);
    }
}

// ---------------------------------------------------------------------------
// GEMM 1: HMMA bf16x3 GEMM-NT, block tile 128x96, 8 warps (4m x 2n), 32x48 warp
// tile, K=24 chunks of 32, 4-stage cp.async, single sync/chunk, dual-output.
// On the C1 (Wh) side, the 96-col tile == one head: epilogue also computes
// s1[i,head] / s2[i,head] dot products via shfl + atomicAdd (avec != null).
// ---------------------------------------------------------------------------
#define TILE_A  8192            // 128 x 32 bf16
#define TILE_B  6144            // 96 x 32 bf16
#define STAGE_SZ (2*TILE_A + 2*TILE_B)   // 28672
#define GEMM_SMEM (4 * STAGE_SZ)         // 114688

__device__ __forceinline__ void issue_chunk(uint32_t sb,
                                            const __nv_bfloat16* Ahi, const __nv_bfloat16* Alo,
                                            const __nv_bfloat16* Bhi, const __nv_bfloat16* Blo,
                                            int m0, int n0, int kc, int tid) {
    const size_t kofs = (size_t)kc * 32;
#pragma unroll
    for (int p = 0; p < 2; p++) {
        uint32_t idx = tid + p * 256;           // A: 512 16B units
        uint32_t r = idx >> 2, c = idx & 3;
        uint32_t d = sw_off(r, c);
        size_t g = (size_t)(m0 + r) * 768 + kofs + c * 8;
        cp_async16(sb + d,          Ahi + g);
        cp_async16(sb + TILE_A + d, Alo + g);
    }
    {
        uint32_t r = tid >> 2, c = tid & 3;     // B: first 256 of 384 units
        uint32_t d = sw_off(r, c);
        size_t g = (size_t)(n0 + r) * 768 + kofs + c * 8;
        cp_async16(sb + 2 * TILE_A + d,          Bhi + g);
        cp_async16(sb + 2 * TILE_A + TILE_B + d, Blo + g);
    }
    if (tid < 128) {
        uint32_t idx = tid + 256;
        uint32_t r = idx >> 2, c = idx & 3;
        uint32_t d = sw_off(r, c);
        size_t g = (size_t)(n0 + r) * 768 + kofs + c * 8;
        cp_async16(sb + 2 * TILE_A + d,          Bhi + g);
        cp_async16(sb + 2 * TILE_A + TILE_B + d, Blo + g);
    }
    CP_COMMIT();
}

__global__ __launch_bounds__(256, 2) void gemm_hmma_kernel(
    const __nv_bfloat16* __restrict__ Ahi, const __nv_bfloat16* __restrict__ Alo,
    const __nv_bfloat16* __restrict__ B1hi, const __nv_bfloat16* __restrict__ B1lo,
    float* __restrict__ C1, const float* __restrict__ bias1, const float* __restrict__ add1,
    const __nv_bfloat16* __restrict__ B2hi, const __nv_bfloat16* __restrict__ B2lo,
    float* __restrict__ C2, const float* __restrict__ bias2,
    int nx1, const float* __restrict__ avec)
{
    extern __shared__ __align__(128) char smem[];
    const uint32_t sbase = smem_to_u32(smem);
    const int tid = threadIdx.x;
    const int wid = tid >> 5, lane = tid & 31;
    const int wm = wid >> 1;            // 0..3  -> 32 rows each
    const int wn = wid & 1;             // 0..1  -> 48 cols each

    int bx = blockIdx.x;
    const __nv_bfloat16 *Bhi, *Blo;
    float* C; const float* bias; const float* add;
    const float* av;
    int head;
    if (bx < nx1) { Bhi = B1hi; Blo = B1lo; C = C1; bias = bias1; add = add1; av = avec; head = bx; }
    else          { Bhi = B2hi; Blo = B2lo; C = C2; bias = bias2; add = nullptr; av = nullptr; bx -= nx1; head = bx; }
    const int m0 = blockIdx.y * 128;
    const int n0 = bx * 96;

    float acc[2][6][4];
#pragma unroll
    for (int i = 0; i < 2; i++)
#pragma unroll
        for (int j = 0; j < 6; j++)
#pragma unroll
            for (int q = 0; q < 4; q++) acc[i][j][q] = 0.f;

    const uint32_t a_r = wm * 32 + (lane & 15);
    const uint32_t b_r = wn * 48 + (lane & 15);
    const uint32_t kq  = (lane >> 4);

    issue_chunk(sbase,                Ahi, Alo, Bhi, Blo, m0, n0, 0, tid);
    issue_chunk(sbase + STAGE_SZ,     Ahi, Alo, Bhi, Blo, m0, n0, 1, tid);
    issue_chunk(sbase + 2 * STAGE_SZ, Ahi, Alo, Bhi, Blo, m0, n0, 2, tid);

#pragma unroll 1
    for (int kc = 0; kc < 24; kc++) {
        if (kc < 22)      { CP_WAIT(2); }
        else if (kc < 23) { CP_WAIT(1); }
        else              { CP_WAIT(0); }
        __syncthreads();

        if (kc + 3 < 24)
            issue_chunk(sbase + ((kc + 3) & 3) * STAGE_SZ, Ahi, Alo, Bhi, Blo, m0, n0, kc + 3, tid);

        const uint32_t sb = sbase + (kc & 3) * STAGE_SZ;
#pragma unroll
        for (int ks = 0; ks < 2; ks++) {
            const uint32_t chunk = ks * 2 + kq;
            uint32_t ahi[2][4], alo[2][4];
#pragma unroll
            for (int mf = 0; mf < 2; mf++) {
                uint32_t off = sw_off(a_r + mf * 16, chunk);
                ldsm_x4(ahi[mf], sb + off);
                ldsm_x4(alo[mf], sb + TILE_A + off);
            }
#pragma unroll
            for (int g = 0; g < 3; g++) {
                uint32_t off = sw_off(b_r + g * 16, chunk);
                uint32_t bhi[4], blo[4];
                ldsm_x4(bhi, sb + 2 * TILE_A + off);
                ldsm_x4(blo, sb + 2 * TILE_A + TILE_B + off);
#pragma unroll
                for (int term = 0; term < 3; term++)
#pragma unroll
                    for (int mf = 0; mf < 2; mf++)
#pragma unroll
                        for (int o = 0; o < 2; o++) {
                            int nf = g * 2 + o;
                            if (term == 0)
                                mma16816(acc[mf][nf], ahi[mf], bhi[o], bhi[o + 2]);
                            else if (term == 1)
                                mma16816(acc[mf][nf], ahi[mf], blo[o], blo[o + 2]);
                            else
                                mma16816(acc[mf][nf], alo[mf], bhi[o], bhi[o + 2]);
                        }
            }
        }
    }

    // epilogue (+ fused s1/s2 on the Wh side)
    const int er = m0 + wm * 32 + (lane >> 2);
    const int ec0 = n0 + wn * 48 + 2 * (lane & 3);
    const int cl0 = wn * 48 + 2 * (lane & 3);      // col within head
    float p1[2][2] = {{0.f, 0.f}, {0.f, 0.f}};
    float p2[2][2] = {{0.f, 0.f}, {0.f, 0.f}};
#pragma unroll
    for (int mf = 0; mf < 2; mf++) {
#pragma unroll
        for (int half = 0; half < 2; half++) {
            int r = er + mf * 16 + half * 8;
#pragma unroll
            for (int nf = 0; nf < 6; nf++) {
                int c = ec0 + nf * 8;
                float2 v;
                v.x = acc[mf][nf][half * 2 + 0];
                v.y = acc[mf][nf][half * 2 + 1];
                if (bias) {
                    float2 b = *reinterpret_cast<const float2*>(bias + c);
                    v.x += b.x; v.y += b.y;
                }
                if (add) {
                    float2 a2 = *reinterpret_cast<const float2*>(add + (size_t)r * 768 + c);
                    v.x += a2.x; v.y += a2.y;
                }
                *reinterpret_cast<float2*>(C + (size_t)r * 768 + c) = v;
                if (av) {
                    int cl = cl0 + nf * 8;
                    p1[mf][half] += v.x * __ldg(av + cl) + v.y * __ldg(av + cl + 1);
                    p2[mf][half] += v.x * __ldg(av + 96 + cl) + v.y * __ldg(av + 96 + cl + 1);
                }
            }
        }
    }
    if (av) {
#pragma unroll
        for (int mf = 0; mf < 2; mf++)
#pragma unroll
            for (int half = 0; half < 2; half++) {
                float q1 = p1[mf][half], q2 = p2[mf][half];
                q1 += __shfl_xor_sync(0xFFFFFFFFu, q1, 1);
                q1 += __shfl_xor_sync(0xFFFFFFFFu, q1, 2);
                q2 += __shfl_xor_sync(0xFFFFFFFFu, q2, 1);
                q2 += __shfl_xor_sync(0xFFFFFFFFu, q2, 2);
                if ((lane & 3) == 0) {
                    int r = er + mf * 16 + half * 8;
                    atomicAdd(&g_s1[r * 8 + head], q1);
                    atomicAdd(&g_s2[r * 8 + head], q2);
                }
            }
    }
}

// ---------------------------------------------------------------------------
// GEMM 2: same algorithm, block tile 64x96 (grid 8x32 = 256 CTAs = full wave),
// single output with bias + add. Warp tile 16x48 (8 warps: 4m x 2n).
// ---------------------------------------------------------------------------
#define TILE_A64 4096           // 64 x 32 bf16
#define STAGE64 (2*TILE_A64 + 2*TILE_B)  // 20480
#define GEMM_SMEM64 (4 * STAGE64)        // 81920

__device__ __forceinline__ void issue_chunk64(uint32_t sb,
                                              const __nv_bfloat16* Ahi, const __nv_bfloat16* Alo,
                                              const __nv_bfloat16* Bhi, const __nv_bfloat16* Blo,
                                              int m0, int n0, int kc, int tid) {
    const size_t kofs = (size_t)kc * 32;
    {
        uint32_t r = tid >> 2, c = tid & 3;     // A: 256 16B units (64 rows x 4)
        uint32_t d = sw_off(r, c);
        size_t g = (size_t)(m0 + r) * 768 + kofs + c * 8;
        cp_async16(sb + d,           Ahi + g);
        cp_async16(sb + TILE_A64 + d, Alo + g);
    }
    {
        uint32_t r = tid >> 2, c = tid & 3;     // B: first 256 of 384 units
        uint32_t d = sw_off(r, c);
        size_t g = (size_t)(n0 + r) * 768 + kofs + c * 8;
        cp_async16(sb + 2 * TILE_A64 + d,          Bhi + g);
        cp_async16(sb + 2 * TILE_A64 + TILE_B + d, Blo + g);
    }
    if (tid < 128) {
        uint32_t idx = tid + 256;
        uint32_t r = idx >> 2, c = idx & 3;
        uint32_t d = sw_off(r, c);
        size_t g = (size_t)(n0 + r) * 768 + kofs + c * 8;
        cp_async16(sb + 2 * TILE_A64 + d,          Bhi + g);
        cp_async16(sb + 2 * TILE_A64 + TILE_B + d, Blo + g);
    }
    CP_COMMIT();
}

__global__ __launch_bounds__(256, 2) void gemm_hmma64_kernel(
    const __nv_bfloat16* __restrict__ Ahi, const __nv_bfloat16* __restrict__ Alo,
    const __nv_bfloat16* __restrict__ Bhi, const __nv_bfloat16* __restrict__ Blo,
    float* __restrict__ C, const float* __restrict__ bias, const float* __restrict__ add)
{
    extern __shared__ __align__(128) char smem[];
    const uint32_t sbase = smem_to_u32(smem);
    const int tid = threadIdx.x;
    const int wid = tid >> 5, lane = tid & 31;
    const int wm = wid >> 1;            // 0..3 -> 16 rows each
    const int wn = wid & 1;             // 0..1 -> 48 cols each

    const int m0 = blockIdx.y * 64;
    const int n0 = blockIdx.x * 96;

    float acc[6][4];
#pragma unroll
    for (int j = 0; j < 6; j++)
#pragma unroll
        for (int q = 0; q < 4; q++) acc[j][q] = 0.f;

    const uint32_t a_r = wm * 16 + (lane & 15);
    const uint32_t b_r = wn * 48 + (lane & 15);
    const uint32_t kq  = (lane >> 4);

    issue_chunk64(sbase,             Ahi, Alo, Bhi, Blo, m0, n0, 0, tid);
    issue_chunk64(sbase + STAGE64,   Ahi, Alo, Bhi, Blo, m0, n0, 1, tid);
    issue_chunk64(sbase + 2*STAGE64, Ahi, Alo, Bhi, Blo, m0, n0, 2, tid);

#pragma unroll 1
    for (int kc = 0; kc < 24; kc++) {
        if (kc < 22)      { CP_WAIT(2); }
        else if (kc < 23) { CP_WAIT(1); }
        else              { CP_WAIT(0); }
        __syncthreads();

        if (kc + 3 < 24)
            issue_chunk64(sbase + ((kc + 3) & 3) * STAGE64, Ahi, Alo, Bhi, Blo, m0, n0, kc + 3, tid);

        const uint32_t sb = sbase + (kc & 3) * STAGE64;
#pragma unroll
        for (int ks = 0; ks < 2; ks++) {
            const uint32_t chunk = ks * 2 + kq;
            uint32_t ahi[4], alo[4];
            {
                uint32_t off = sw_off(a_r, chunk);
                ldsm_x4(ahi, sb + off);
                ldsm_x4(alo, sb + TILE_A64 + off);
            }
#pragma unroll
            for (int g = 0; g < 3; g++) {
                uint32_t off = sw_off(b_r + g * 16, chunk);
                uint32_t bhi[4], blo[4];
                ldsm_x4(bhi, sb + 2 * TILE_A64 + off);
                ldsm_x4(blo, sb + 2 * TILE_A64 + TILE_B + off);
#pragma unroll
                for (int term = 0; term < 3; term++)
#pragma unroll
                    for (int o = 0; o < 2; o++) {
                        int nf = g * 2 + o;
                        if (term == 0)
                            mma16816(acc[nf], ahi, bhi[o], bhi[o + 2]);
                        else if (term == 1)
                            mma16816(acc[nf], ahi, blo[o], blo[o + 2]);
                        else
                            mma16816(acc[nf], alo, bhi[o], bhi[o + 2]);
                    }
            }
        }
    }

    const int er = m0 + wm * 16 + (lane >> 2);
    const int ec0 = n0 + wn * 48 + 2 * (lane & 3);
#pragma unroll
    for (int half = 0; half < 2; half++) {
        int r = er + half * 8;
#pragma unroll
        for (int nf = 0; nf < 6; nf++) {
            int c = ec0 + nf * 8;
            float2 v;
            v.x = acc[nf][half * 2 + 0];
            v.y = acc[nf][half * 2 + 1];
            float2 b = *reinterpret_cast<const float2*>(bias + c);
            v.x += b.x; v.y += b.y;
            float2 a2 = *reinterpret_cast<const float2*>(add + (size_t)r * 768 + c);
            v.x += a2.x; v.y += a2.y;
            *reinterpret_cast<float2*>(C + (size_t)r * 768 + c) = v;
        }
    }
}

// ---------------------------------------------------------------------------
// Grouped attention. grid(32,32): x=group, y=i-tile; 8 warps = heads.
// 2-row i-tiles (~32 tiles/group -> all 1024 blocks busy), 2-way j unroll.
// ---------------------------------------------------------------------------
#define ITILE 2
__global__ __launch_bounds__(256) void attn_kernel() {
    int g = blockIdx.x;
    int start = g_gstart[g], end = g_gstart[g + 1];
    int len = end - start;
    int tid = threadIdx.x;
    int h = tid >> 5, l = tid & 31;
    __shared__ float s1s[ITILE][8];
    __shared__ int ilist[ITILE];

    for (int t = blockIdx.y; t * ITILE < len; t += gridDim.y) {
        __syncthreads();
        int ni = len - t * ITILE; if (ni > ITILE) ni = ITILE;
        if (tid < ITILE) {
            int src = t * ITILE + tid;
            ilist[tid] = g_glist[start + (src < len ? src : 0)];
        }
        __syncthreads();
        if (tid < ITILE * 8) s1s[tid >> 3][tid & 7] = g_s1[ilist[tid >> 3] * 8 + (tid & 7)];
        __syncthreads();

        float acc[ITILE][3];
        float Z[ITILE];
#pragma unroll
        for (int ii = 0; ii < ITILE; ii++) {
            Z[ii] = 0.f; acc[ii][0] = 0.f; acc[ii][1] = 0.f; acc[ii][2] = 0.f;
        }
        const float* whb = g_Wh + h * 96 + l;
        int idx = start;
        for (; idx + 1 < end; idx += 2) {
            int j0 = __ldg(&g_glist[idx]);
            int j1 = __ldg(&g_glist[idx + 1]);
            float s2v0 = __ldg(&g_s2[j0 * 8 + h]);
            float s2v1 = __ldg(&g_s2[j1 * 8 + h]);
            const float* wp0 = whb + (size_t)j0 * 768;
            const float* wp1 = whb + (size_t)j1 * 768;
            float w00 = __ldg(wp0), w01 = __ldg(wp0 + 32), w02 = __ldg(wp0 + 64);
            float w10 = __ldg(wp1), w11 = __ldg(wp1 + 32), w12 = __ldg(wp1 + 64);
            int b0 = j0 >> 8, b1 = j1 >> 8;
#pragma unroll
            for (int ii = 0; ii < ITILE; ii++) {
                float x0 = s1s[ii][b0] + s2v0;
                float x1 = s1s[ii][b1] + s2v1;
                x0 = (x0 >= 0.f) ? x0 : 0.2f * x0;
                x1 = (x1 >= 0.f) ? x1 : 0.2f * x1;
                float wg0 = ex2f(x0 * K_EXP2);
                float wg1 = ex2f(x1 * K_EXP2);
                Z[ii] += wg0 + wg1;
                acc[ii][0] += wg0 * w00 + wg1 * w10;
                acc[ii][1] += wg0 * w01 + wg1 * w11;
                acc[ii][2] += wg0 * w02 + wg1 * w12;
            }
        }
        if (idx < end) {
            int j = __ldg(&g_glist[idx]);
            float s2v = __ldg(&g_s2[j * 8 + h]);
            const float* wp = whb + (size_t)j * 768;
            float w0 = __ldg(wp), w1 = __ldg(wp + 32), w2 = __ldg(wp + 64);
            int b = j >> 8;
#pragma unroll
            for (int ii = 0; ii < ITILE; ii++) {
                float x = s1s[ii][b] + s2v;
                x = (x >= 0.f) ? x : 0.2f * x;
                float wg = ex2f(x * K_EXP2);
                Z[ii] += wg;
                acc[ii][0] += wg * w0;
                acc[ii][1] += wg * w1;
                acc[ii][2] += wg * w2;
            }
        }
#pragma unroll
        for (int ii = 0; ii < ITILE; ii++) {
            if (ii < ni) {
                float inv = 1.f / Z[ii];
                size_t o = (size_t)ilist[ii] * 768 + h * 96 + l;
#pragma unroll
                for (int kc = 0; kc < 3; kc++) {
                    float v = acc[ii][kc] * inv;
                    __nv_bfloat16 hi, lo;
                    split_bf16(v, hi, lo);
                    g_athi[o + kc * 32] = hi;
                    g_atlo[o + kc * 32] = lo;
                }
            }
        }
    }
}

// ---------------------------------------------------------------------------
extern "C" void kernel_launch(void* const* d_in, const int* in_sizes, int n_in,
                              void* d_out, int out_size) {
    const float* eh     = (const float*)d_in[0];
    const float* er     = (const float*)d_in[1];
    const float* et     = (const float*)d_in[2];
    const int*   h_id   = (const int*)d_in[3];
    const float* W_w    = (const float*)d_in[4];
    const float* a      = (const float*)d_in[5];
    const float* proj_w = (const float*)d_in[6];
    const float* proj_b = (const float*)d_in[7];
    const float* skip_w = (const float*)d_in[8];
    const float* skip_b = (const float*)d_in[9];
    float* out = (float*)d_out;

    float *pWh, *pskip;
    __nv_bfloat16 *pehi, *pelo, *pwwhi, *pwwlo, *pskhi, *psklo, *ppjhi, *ppjlo, *pathi, *patlo;
    cudaGetSymbolAddress((void**)&pWh,   g_Wh);
    cudaGetSymbolAddress((void**)&pskip, g_skip);
    cudaGetSymbolAddress((void**)&pehi,  g_ehi);
    cudaGetSymbolAddress((void**)&pelo,  g_elo);
    cudaGetSymbolAddress((void**)&pwwhi, g_wwhi);
    cudaGetSymbolAddress((void**)&pwwlo, g_wwlo);
    cudaGetSymbolAddress((void**)&pskhi, g_skhi);
    cudaGetSymbolAddress((void**)&psklo, g_sklo);
    cudaGetSymbolAddress((void**)&ppjhi, g_pjhi);
    cudaGetSymbolAddress((void**)&ppjlo, g_pjlo);
    cudaGetSymbolAddress((void**)&pathi, g_athi);
    cudaGetSymbolAddress((void**)&patlo, g_atlo);

    cudaFuncSetAttribute(gemm_hmma_kernel,
                         cudaFuncAttributeMaxDynamicSharedMemorySize, GEMM_SMEM);
    cudaFuncSetAttribute(gemm_hmma64_kernel,
                         cudaFuncAttributeMaxDynamicSharedMemorySize, GEMM_SMEM64);

    // operand prep (one launch) + group lists (also zeroes s1/s2)
    fused_prep_kernel<<<1536 + 3 * WQ / 256, 256>>>(eh, er, et, W_w, skip_w, proj_w);
    build_groups_kernel<<<1, 1024>>>(h_id);

    // GEMM 1 (dual): Wh = e @ W_w^T (+ fused s1/s2) ; skip = e @ skip_w^T + skip_b
    gemm_hmma_kernel<<<dim3(16, 16), 256, GEMM_SMEM>>>(
        pehi, pelo,
        pwwhi, pwwlo, pWh, nullptr, nullptr,
        pskhi, psklo, pskip, skip_b, 8, a);

    // grouped attention -> bf16 hi/lo (2-row tiles, 1024 blocks)
    attn_kernel<<<dim3(32, 32), 256>>>();

    // GEMM 2: out = att @ proj_w^T + proj_b + skip (64x96 tiles, full wave)
    gemm_hmma64_kernel<<<dim3(8, 32), 256, GEMM_SMEM64>>>(
        pathi, patlo, ppjhi, ppjlo, out, proj_b, pskip);
}

// round 16
// speedup vs baseline: 1.0663x; 1.0663x over previous
#include <cuda_runtime.h>
#include <cuda_bf16.h>
#include <cstdint>

// ---------------- problem constants ----------------
#define NN 2048
#define EMB 768
#define HH 8
#define DD 96
// SCALE*log2(e) = (1/sqrt(96)) * 1.4426950408889634
#define K_EXP2 0.14724447f

// ---------------- device scratch (no allocs allowed) ----------------
__device__ __align__(16) float g_Wh[NN * EMB];
__device__ __align__(16) float g_skip[NN * EMB];
__device__ __align__(16) float g_s1[NN * HH];
__device__ __align__(16) float g_s2[NN * HH];
__device__ int   g_glist[NN];
__device__ int   g_gstart[33];

// bf16 hi/lo split operands
__device__ __align__(16) __nv_bfloat16 g_ehi[NN * EMB];
__device__ __align__(16) __nv_bfloat16 g_elo[NN * EMB];
__device__ __align__(16) __nv_bfloat16 g_wwhi[EMB * EMB];
__device__ __align__(16) __nv_bfloat16 g_wwlo[EMB * EMB];
__device__ __align__(16) __nv_bfloat16 g_skhi[EMB * EMB];
__device__ __align__(16) __nv_bfloat16 g_sklo[EMB * EMB];
__device__ __align__(16) __nv_bfloat16 g_pjhi[EMB * EMB];
__device__ __align__(16) __nv_bfloat16 g_pjlo[EMB * EMB];
__device__ __align__(16) __nv_bfloat16 g_athi[NN * EMB];
__device__ __align__(16) __nv_bfloat16 g_atlo[NN * EMB];

// ---------------- low-level helpers ----------------
__device__ __forceinline__ uint32_t smem_to_u32(const void* p) {
    uint32_t a;
    asm("{ .reg .u64 t; cvta.to.shared.u64 t, %1; cvt.u32.u64 %0, t; }" : "=r"(a) : "l"(p));
    return a;
}
__device__ __forceinline__ void cp_async16(uint32_t dst, const void* src) {
    asm volatile("cp.async.cg.shared.global [%0], [%1], 16;" :: "r"(dst), "l"(src));
}
#define CP_COMMIT() asm volatile("cp.async.commit_group;")
#define CP_WAIT(n)  asm volatile("cp.async.wait_group %0;" :: "n"(n))

__device__ __forceinline__ void ldsm_x4(uint32_t* r, uint32_t addr) {
    asm volatile("ldmatrix.sync.aligned.m8n8.x4.shared.b16 {%0,%1,%2,%3}, [%4];"
                 : "=r"(r[0]), "=r"(r[1]), "=r"(r[2]), "=r"(r[3]) : "r"(addr));
}
__device__ __forceinline__ void mma16816(float* d, const uint32_t* a, uint32_t b0, uint32_t b1) {
    asm volatile(
        "mma.sync.aligned.m16n8k16.row.col.f32.bf16.bf16.f32 "
        "{%0,%1,%2,%3}, {%4,%5,%6,%7}, {%8,%9}, {%0,%1,%2,%3};"
        : "+f"(d[0]), "+f"(d[1]), "+f"(d[2]), "+f"(d[3])
        : "r"(a[0]), "r"(a[1]), "r"(a[2]), "r"(a[3]), "r"(b0), "r"(b1));
}
__device__ __forceinline__ float ex2f(float x) {
    float y;
    asm("ex2.approx.ftz.f32 %0, %1;" : "=f"(y) : "f"(x));
    return y;
}
__device__ __forceinline__ void split_bf16(float v, __nv_bfloat16& hi, __nv_bfloat16& lo) {
    hi = __float2bfloat16(v);
    lo = __float2bfloat16(v - __bfloat162float(hi));
}
__device__ __forceinline__ uint32_t pack2bf(__nv_bfloat16 a, __nv_bfloat16 b) {
    return (uint32_t)__bfloat16_as_ushort(a) | ((uint32_t)__bfloat16_as_ushort(b) << 16);
}
// swizzled byte offset inside a (rows x 32 bf16) tile: row stride 64B, 16B chunks
__device__ __forceinline__ uint32_t sw_off(uint32_t r, uint32_t chunk) {
    return r * 64u + ((chunk ^ ((r >> 1) & 3u)) << 4);
}

// ---------------------------------------------------------------------------
// fused prep: blocks [0,1536) pack e -> bf16 hi/lo; [1536, 3264) split weights
// ---------------------------------------------------------------------------
#define WQ (EMB * EMB / 4)   // 147456 float4 units per matrix
__global__ void fused_prep_kernel(const float* __restrict__ eh,
                                  const float* __restrict__ er,
                                  const float* __restrict__ et,
                                  const float* __restrict__ w0,
                                  const float* __restrict__ w1,
                                  const float* __restrict__ w2) {
    int bid = blockIdx.x;
    const float* src;
    __nv_bfloat16 *hi, *lo;
    int ridx;
    if (bid < 1536) {
        int idx4 = bid * 256 + threadIdx.x;      // < 2048*192
        int row = idx4 / 192;
        int c4 = idx4 - row * 192;
        if (c4 < 64)       src = eh + row * 256 + c4 * 4;
        else if (c4 < 128) src = er + row * 256 + (c4 - 64) * 4;
        else               src = et + row * 256 + (c4 - 128) * 4;
        hi = g_ehi; lo = g_elo; ridx = idx4;
    } else {
        int idx4 = (bid - 1536) * 256 + threadIdx.x;   // < 3*WQ
        int r;
        if (idx4 < WQ)          { src = w0; hi = g_wwhi; lo = g_wwlo; r = idx4; }
        else if (idx4 < 2 * WQ) { src = w1; hi = g_skhi; lo = g_sklo; r = idx4 - WQ; }
        else                    { src = w2; hi = g_pjhi; lo = g_pjlo; r = idx4 - 2 * WQ; }
        src = src + (size_t)r * 4; ridx = r;
    }
    float4 v = *reinterpret_cast<const float4*>(src);
    __nv_bfloat16 h0, l0, h1, l1, h2, l2, h3, l3;
    split_bf16(v.x, h0, l0); split_bf16(v.y, h1, l1);
    split_bf16(v.z, h2, l2); split_bf16(v.w, h3, l3);
    uint2 hv, lv;
    hv.x = pack2bf(h0, h1); hv.y = pack2bf(h2, h3);
    lv.x = pack2bf(l0, l1); lv.y = pack2bf(l2, l3);
    *reinterpret_cast<uint2*>(hi + (size_t)ridx * 4) = hv;
    *reinterpret_cast<uint2*>(lo + (size_t)ridx * 4) = lv;
}

// ---------------------------------------------------------------------------
// group lists via warp-ballot compaction + zero s1/s2 accumulators
// ---------------------------------------------------------------------------
__global__ void build_groups_kernel(const int* __restrict__ h_id) {
    __shared__ int hs[NN];
    __shared__ int st[33];
    int tid = threadIdx.x;
    for (int i = tid; i < NN * HH; i += 1024) { g_s1[i] = 0.f; g_s2[i] = 0.f; }
    hs[tid] = h_id[tid];
    hs[tid + 1024] = h_id[tid + 1024];
    __syncthreads();
    int w = tid >> 5, l = tid & 31;
    int cnt = 0;
    for (int base = 0; base < NN; base += 32) {
        unsigned m = __ballot_sync(0xFFFFFFFFu, hs[base + l] == w);
        cnt += __popc(m);
    }
    if (l == 0) st[w + 1] = cnt;
    __syncthreads();
    if (tid == 0) {
        st[0] = 0;
        for (int g = 1; g <= 32; g++) st[g] += st[g - 1];
    }
    __syncthreads();
    if (tid < 33) g_gstart[tid] = st[tid];
    int pos = st[w];
    for (int base = 0; base < NN; base += 32) {
        int j = base + l;
        bool hit = (hs[j] == w);
        unsigned m = __ballot_sync(0xFFFFFFFFu, hit);
        if (hit) g_glist[pos + __popc(m & ((1u << l) - 1u))] = j;
        pos += __popc(m);
    }
}

// ---------------------------------------------------------------------------
// GEMM 1: HMMA bf16x3 GEMM-NT, block tile 128x96, 8 warps (4m x 2n), 32x48 warp
// tile, K=24 chunks of 32, 4-stage cp.async, single sync/chunk, dual-output.
// On the C1 (Wh) side, the 96-col tile == one head: epilogue also computes
// s1[i,head] / s2[i,head] dot products via shfl + atomicAdd (avec != null).
// ---------------------------------------------------------------------------
#define TILE_A  8192            // 128 x 32 bf16
#define TILE_B  6144            // 96 x 32 bf16
#define STAGE_SZ (2*TILE_A + 2*TILE_B)   // 28672
#define GEMM_SMEM (4 * STAGE_SZ)         // 114688

__device__ __forceinline__ void issue_chunk(uint32_t sb,
                                            const __nv_bfloat16* Ahi, const __nv_bfloat16* Alo,
                                            const __nv_bfloat16* Bhi, const __nv_bfloat16* Blo,
                                            int m0, int n0, int kc, int tid) {
    const size_t kofs = (size_t)kc * 32;
#pragma unroll
    for (int p = 0; p < 2; p++) {
        uint32_t idx = tid + p * 256;           // A: 512 16B units
        uint32_t r = idx >> 2, c = idx & 3;
        uint32_t d = sw_off(r, c);
        size_t g = (size_t)(m0 + r) * 768 + kofs + c * 8;
        cp_async16(sb + d,          Ahi + g);
        cp_async16(sb + TILE_A + d, Alo + g);
    }
    {
        uint32_t r = tid >> 2, c = tid & 3;     // B: first 256 of 384 units
        uint32_t d = sw_off(r, c);
        size_t g = (size_t)(n0 + r) * 768 + kofs + c * 8;
        cp_async16(sb + 2 * TILE_A + d,          Bhi + g);
        cp_async16(sb + 2 * TILE_A + TILE_B + d, Blo + g);
    }
    if (tid < 128) {
        uint32_t idx = tid + 256;
        uint32_t r = idx >> 2, c = idx & 3;
        uint32_t d = sw_off(r, c);
        size_t g = (size_t)(n0 + r) * 768 + kofs + c * 8;
        cp_async16(sb + 2 * TILE_A + d,          Bhi + g);
        cp_async16(sb + 2 * TILE_A + TILE_B + d, Blo + g);
    }
    CP_COMMIT();
}

__global__ __launch_bounds__(256, 2) void gemm_hmma_kernel(
    const __nv_bfloat16* __restrict__ Ahi, const __nv_bfloat16* __restrict__ Alo,
    const __nv_bfloat16* __restrict__ B1hi, const __nv_bfloat16* __restrict__ B1lo,
    float* __restrict__ C1, const float* __restrict__ bias1, const float* __restrict__ add1,
    const __nv_bfloat16* __restrict__ B2hi, const __nv_bfloat16* __restrict__ B2lo,
    float* __restrict__ C2, const float* __restrict__ bias2,
    int nx1, const float* __restrict__ avec)
{
    extern __shared__ __align__(128) char smem[];
    const uint32_t sbase = smem_to_u32(smem);
    const int tid = threadIdx.x;
    const int wid = tid >> 5, lane = tid & 31;
    const int wm = wid >> 1;            // 0..3  -> 32 rows each
    const int wn = wid & 1;             // 0..1  -> 48 cols each

    int bx = blockIdx.x;
    const __nv_bfloat16 *Bhi, *Blo;
    float* C; const float* bias; const float* add;
    const float* av;
    int head;
    if (bx < nx1) { Bhi = B1hi; Blo = B1lo; C = C1; bias = bias1; add = add1; av = avec; head = bx; }
    else          { Bhi = B2hi; Blo = B2lo; C = C2; bias = bias2; add = nullptr; av = nullptr; bx -= nx1; head = bx; }
    const int m0 = blockIdx.y * 128;
    const int n0 = bx * 96;

    float acc[2][6][4];
#pragma unroll
    for (int i = 0; i < 2; i++)
#pragma unroll
        for (int j = 0; j < 6; j++)
#pragma unroll
            for (int q = 0; q < 4; q++) acc[i][j][q] = 0.f;

    const uint32_t a_r = wm * 32 + (lane & 15);
    const uint32_t b_r = wn * 48 + (lane & 15);
    const uint32_t kq  = (lane >> 4);

    issue_chunk(sbase,                Ahi, Alo, Bhi, Blo, m0, n0, 0, tid);
    issue_chunk(sbase + STAGE_SZ,     Ahi, Alo, Bhi, Blo, m0, n0, 1, tid);
    issue_chunk(sbase + 2 * STAGE_SZ, Ahi, Alo, Bhi, Blo, m0, n0, 2, tid);

#pragma unroll 1
    for (int kc = 0; kc < 24; kc++) {
        if (kc < 22)      { CP_WAIT(2); }
        else if (kc < 23) { CP_WAIT(1); }
        else              { CP_WAIT(0); }
        __syncthreads();

        if (kc + 3 < 24)
            issue_chunk(sbase + ((kc + 3) & 3) * STAGE_SZ, Ahi, Alo, Bhi, Blo, m0, n0, kc + 3, tid);

        const uint32_t sb = sbase + (kc & 3) * STAGE_SZ;
#pragma unroll
        for (int ks = 0; ks < 2; ks++) {
            const uint32_t chunk = ks * 2 + kq;
            uint32_t ahi[2][4], alo[2][4];
#pragma unroll
            for (int mf = 0; mf < 2; mf++) {
                uint32_t off = sw_off(a_r + mf * 16, chunk);
                ldsm_x4(ahi[mf], sb + off);
                ldsm_x4(alo[mf], sb + TILE_A + off);
            }
#pragma unroll
            for (int g = 0; g < 3; g++) {
                uint32_t off = sw_off(b_r + g * 16, chunk);
                uint32_t bhi[4], blo[4];
                ldsm_x4(bhi, sb + 2 * TILE_A + off);
                ldsm_x4(blo, sb + 2 * TILE_A + TILE_B + off);
#pragma unroll
                for (int term = 0; term < 3; term++)
#pragma unroll
                    for (int mf = 0; mf < 2; mf++)
#pragma unroll
                        for (int o = 0; o < 2; o++) {
                            int nf = g * 2 + o;
                            if (term == 0)
                                mma16816(acc[mf][nf], ahi[mf], bhi[o], bhi[o + 2]);
                            else if (term == 1)
                                mma16816(acc[mf][nf], ahi[mf], blo[o], blo[o + 2]);
                            else
                                mma16816(acc[mf][nf], alo[mf], bhi[o], bhi[o + 2]);
                        }
            }
        }
    }

    // epilogue (+ fused s1/s2 on the Wh side)
    const int er = m0 + wm * 32 + (lane >> 2);
    const int ec0 = n0 + wn * 48 + 2 * (lane & 3);
    const int cl0 = wn * 48 + 2 * (lane & 3);      // col within head
    float p1[2][2] = {{0.f, 0.f}, {0.f, 0.f}};
    float p2[2][2] = {{0.f, 0.f}, {0.f, 0.f}};
#pragma unroll
    for (int mf = 0; mf < 2; mf++) {
#pragma unroll
        for (int half = 0; half < 2; half++) {
            int r = er + mf * 16 + half * 8;
#pragma unroll
            for (int nf = 0; nf < 6; nf++) {
                int c = ec0 + nf * 8;
                float2 v;
                v.x = acc[mf][nf][half * 2 + 0];
                v.y = acc[mf][nf][half * 2 + 1];
                if (bias) {
                    float2 b = *reinterpret_cast<const float2*>(bias + c);
                    v.x += b.x; v.y += b.y;
                }
                if (add) {
                    float2 a2 = *reinterpret_cast<const float2*>(add + (size_t)r * 768 + c);
                    v.x += a2.x; v.y += a2.y;
                }
                *reinterpret_cast<float2*>(C + (size_t)r * 768 + c) = v;
                if (av) {
                    int cl = cl0 + nf * 8;
                    p1[mf][half] += v.x * __ldg(av + cl) + v.y * __ldg(av + cl + 1);
                    p2[mf][half] += v.x * __ldg(av + 96 + cl) + v.y * __ldg(av + 96 + cl + 1);
                }
            }
        }
    }
    if (av) {
#pragma unroll
        for (int mf = 0; mf < 2; mf++)
#pragma unroll
            for (int half = 0; half < 2; half++) {
                float q1 = p1[mf][half], q2 = p2[mf][half];
                q1 += __shfl_xor_sync(0xFFFFFFFFu, q1, 1);
                q1 += __shfl_xor_sync(0xFFFFFFFFu, q1, 2);
                q2 += __shfl_xor_sync(0xFFFFFFFFu, q2, 1);
                q2 += __shfl_xor_sync(0xFFFFFFFFu, q2, 2);
                if ((lane & 3) == 0) {
                    int r = er + mf * 16 + half * 8;
                    atomicAdd(&g_s1[r * 8 + head], q1);
                    atomicAdd(&g_s2[r * 8 + head], q2);
                }
            }
    }
}

// ---------------------------------------------------------------------------
// GEMM 2: same algorithm, block tile 64x96 (grid 8x32 = 256 CTAs = full wave),
// single output with bias + add. Warp tile 16x48 (8 warps: 4m x 2n).
// ---------------------------------------------------------------------------
#define TILE_A64 4096           // 64 x 32 bf16
#define STAGE64 (2*TILE_A64 + 2*TILE_B)  // 20480
#define GEMM_SMEM64 (4 * STAGE64)        // 81920

__device__ __forceinline__ void issue_chunk64(uint32_t sb,
                                              const __nv_bfloat16* Ahi, const __nv_bfloat16* Alo,
                                              const __nv_bfloat16* Bhi, const __nv_bfloat16* Blo,
                                              int m0, int n0, int kc, int tid) {
    const size_t kofs = (size_t)kc * 32;
    {
        uint32_t r = tid >> 2, c = tid & 3;     // A: 256 16B units (64 rows x 4)
        uint32_t d = sw_off(r, c);
        size_t g = (size_t)(m0 + r) * 768 + kofs + c * 8;
        cp_async16(sb + d,           Ahi + g);
        cp_async16(sb + TILE_A64 + d, Alo + g);
    }
    {
        uint32_t r = tid >> 2, c = tid & 3;     // B: first 256 of 384 units
        uint32_t d = sw_off(r, c);
        size_t g = (size_t)(n0 + r) * 768 + kofs + c * 8;
        cp_async16(sb + 2 * TILE_A64 + d,          Bhi + g);
        cp_async16(sb + 2 * TILE_A64 + TILE_B + d, Blo + g);
    }
    if (tid < 128) {
        uint32_t idx = tid + 256;
        uint32_t r = idx >> 2, c = idx & 3;
        uint32_t d = sw_off(r, c);
        size_t g = (size_t)(n0 + r) * 768 + kofs + c * 8;
        cp_async16(sb + 2 * TILE_A64 + d,          Bhi + g);
        cp_async16(sb + 2 * TILE_A64 + TILE_B + d, Blo + g);
    }
    CP_COMMIT();
}

__global__ __launch_bounds__(256, 2) void gemm_hmma64_kernel(
    const __nv_bfloat16* __restrict__ Ahi, const __nv_bfloat16* __restrict__ Alo,
    const __nv_bfloat16* __restrict__ Bhi, const __nv_bfloat16* __restrict__ Blo,
    float* __restrict__ C, const float* __restrict__ bias, const float* __restrict__ add)
{
    extern __shared__ __align__(128) char smem[];
    const uint32_t sbase = smem_to_u32(smem);
    const int tid = threadIdx.x;
    const int wid = tid >> 5, lane = tid & 31;
    const int wm = wid >> 1;            // 0..3 -> 16 rows each
    const int wn = wid & 1;             // 0..1 -> 48 cols each

    const int m0 = blockIdx.y * 64;
    const int n0 = blockIdx.x * 96;

    float acc[6][4];
#pragma unroll
    for (int j = 0; j < 6; j++)
#pragma unroll
        for (int q = 0; q < 4; q++) acc[j][q] = 0.f;

    const uint32_t a_r = wm * 16 + (lane & 15);
    const uint32_t b_r = wn * 48 + (lane & 15);
    const uint32_t kq  = (lane >> 4);

    issue_chunk64(sbase,             Ahi, Alo, Bhi, Blo, m0, n0, 0, tid);
    issue_chunk64(sbase + STAGE64,   Ahi, Alo, Bhi, Blo, m0, n0, 1, tid);
    issue_chunk64(sbase + 2*STAGE64, Ahi, Alo, Bhi, Blo, m0, n0, 2, tid);

#pragma unroll 1
    for (int kc = 0; kc < 24; kc++) {
        if (kc < 22)      { CP_WAIT(2); }
        else if (kc < 23) { CP_WAIT(1); }
        else              { CP_WAIT(0); }
        __syncthreads();

        if (kc + 3 < 24)
            issue_chunk64(sbase + ((kc + 3) & 3) * STAGE64, Ahi, Alo, Bhi, Blo, m0, n0, kc + 3, tid);

        const uint32_t sb = sbase + (kc & 3) * STAGE64;
#pragma unroll
        for (int ks = 0; ks < 2; ks++) {
            const uint32_t chunk = ks * 2 + kq;
            uint32_t ahi[4], alo[4];
            {
                uint32_t off = sw_off(a_r, chunk);
                ldsm_x4(ahi, sb + off);
                ldsm_x4(alo, sb + TILE_A64 + off);
            }
#pragma unroll
            for (int g = 0; g < 3; g++) {
                uint32_t off = sw_off(b_r + g * 16, chunk);
                uint32_t bhi[4], blo[4];
                ldsm_x4(bhi, sb + 2 * TILE_A64 + off);
                ldsm_x4(blo, sb + 2 * TILE_A64 + TILE_B + off);
#pragma unroll
                for (int term = 0; term < 3; term++)
#pragma unroll
                    for (int o = 0; o < 2; o++) {
                        int nf = g * 2 + o;
                        if (term == 0)
                            mma16816(acc[nf], ahi, bhi[o], bhi[o + 2]);
                        else if (term == 1)
                            mma16816(acc[nf], ahi, blo[o], blo[o + 2]);
                        else
                            mma16816(acc[nf], alo, bhi[o], bhi[o + 2]);
                    }
            }
        }
    }

    const int er = m0 + wm * 16 + (lane >> 2);
    const int ec0 = n0 + wn * 48 + 2 * (lane & 3);
#pragma unroll
    for (int half = 0; half < 2; half++) {
        int r = er + half * 8;
#pragma unroll
        for (int nf = 0; nf < 6; nf++) {
            int c = ec0 + nf * 8;
            float2 v;
            v.x = acc[nf][half * 2 + 0];
            v.y = acc[nf][half * 2 + 1];
            float2 b = *reinterpret_cast<const float2*>(bias + c);
            v.x += b.x; v.y += b.y;
            float2 a2 = *reinterpret_cast<const float2*>(add + (size_t)r * 768 + c);
            v.x += a2.x; v.y += a2.y;
            *reinterpret_cast<float2*>(C + (size_t)r * 768 + c) = v;
        }
    }
}

// ---------------------------------------------------------------------------
// Grouped attention, two-phase per 32-j chunk:
//   phase 1: 256 threads cooperatively compute wg[ii][jj][h] into smem
//            (eliminates the 32x lane-replicated lrelu/ex2 chain)
//   phase 2: each (head, lane) thread accumulates 3 LDG + 4 LDS + 16 FMA per j
// ITILE=4 rows, grid(32,16), 8 warps = heads.
// ---------------------------------------------------------------------------
#define ITILE 4
#define JC 32
__global__ __launch_bounds__(256) void attn_kernel() {
    int g = blockIdx.x;
    int start = g_gstart[g], end = g_gstart[g + 1];
    int len = end - start;
    int tid = threadIdx.x;
    int h = tid >> 5, l = tid & 31;
    __shared__ float s1s[ITILE][8];
    __shared__ int ilist[ITILE];
    __shared__ int jls[JC];
    __shared__ float wgs[ITILE][JC * 8];

    for (int t = blockIdx.y; t * ITILE < len; t += gridDim.y) {
        __syncthreads();   // previous tile readers done (ilist/s1s)
        int ni = len - t * ITILE; if (ni > ITILE) ni = ITILE;
        if (tid < ITILE) {
            int src = t * ITILE + tid;
            ilist[tid] = g_glist[start + (src < len ? src : 0)];
        }
        __syncthreads();
        if (tid < ITILE * 8) s1s[tid >> 3][tid & 7] = g_s1[ilist[tid >> 3] * 8 + (tid & 7)];

        float acc[ITILE][3];
        float Z[ITILE];
#pragma unroll
        for (int ii = 0; ii < ITILE; ii++) {
            Z[ii] = 0.f; acc[ii][0] = 0.f; acc[ii][1] = 0.f; acc[ii][2] = 0.f;
        }
        const float* whb = g_Wh + h * 96 + l;

        for (int jc = 0; jc < len; jc += JC) {
            __syncthreads();   // jls/wgs free from previous chunk; s1s visible
            if (tid < JC) {
                int src = jc + tid;
                jls[tid] = g_glist[start + (src < len ? src : len - 1)];
            }
            __syncthreads();
            // phase 1: thread (jj = tid>>3, hh = tid&7) computes ITILE wg values
            {
                int jj = tid >> 3, hh = tid & 7;
                int j = jls[jj];
                float s2v = __ldg(&g_s2[j * 8 + hh]);
                bool valid = (jc + jj < len);
                int b = j >> 8;
#pragma unroll
                for (int ii = 0; ii < ITILE; ii++) {
                    float x = s1s[ii][b] + s2v;
                    x = (x >= 0.f) ? x : 0.2f * x;
                    float wg = valid ? ex2f(x * K_EXP2) : 0.f;
                    wgs[ii][(jj << 3) + hh] = wg;
                }
            }
            __syncthreads();
            // phase 2: weighted accumulation (no MUFU, no lrelu)
            int jn = len - jc; if (jn > JC) jn = JC;
#pragma unroll 2
            for (int jj = 0; jj < jn; jj++) {
                int j = jls[jj];
                const float* wp = whb + (size_t)j * 768;
                float w0 = __ldg(wp), w1 = __ldg(wp + 32), w2 = __ldg(wp + 64);
#pragma unroll
                for (int ii = 0; ii < ITILE; ii++) {
                    float wg = wgs[ii][(jj << 3) + h];
                    Z[ii] += wg;
                    acc[ii][0] += wg * w0;
                    acc[ii][1] += wg * w1;
                    acc[ii][2] += wg * w2;
                }
            }
        }

#pragma unroll
        for (int ii = 0; ii < ITILE; ii++) {
            if (ii < ni) {
                float inv = 1.f / Z[ii];
                size_t o = (size_t)ilist[ii] * 768 + h * 96 + l;
#pragma unroll
                for (int kc = 0; kc < 3; kc++) {
                    float v = acc[ii][kc] * inv;
                    __nv_bfloat16 hi, lo;
                    split_bf16(v, hi, lo);
                    g_athi[o + kc * 32] = hi;
                    g_atlo[o + kc * 32] = lo;
                }
            }
        }
    }
}

// ---------------------------------------------------------------------------
extern "C" void kernel_launch(void* const* d_in, const int* in_sizes, int n_in,
                              void* d_out, int out_size) {
    const float* eh     = (const float*)d_in[0];
    const float* er     = (const float*)d_in[1];
    const float* et     = (const float*)d_in[2];
    const int*   h_id   = (const int*)d_in[3];
    const float* W_w    = (const float*)d_in[4];
    const float* a      = (const float*)d_in[5];
    const float* proj_w = (const float*)d_in[6];
    const float* proj_b = (const float*)d_in[7];
    const float* skip_w = (const float*)d_in[8];
    const float* skip_b = (const float*)d_in[9];
    float* out = (float*)d_out;

    float *pWh, *pskip;
    __nv_bfloat16 *pehi, *pelo, *pwwhi, *pwwlo, *pskhi, *psklo, *ppjhi, *ppjlo, *pathi, *patlo;
    cudaGetSymbolAddress((void**)&pWh,   g_Wh);
    cudaGetSymbolAddress((void**)&pskip, g_skip);
    cudaGetSymbolAddress((void**)&pehi,  g_ehi);
    cudaGetSymbolAddress((void**)&pelo,  g_elo);
    cudaGetSymbolAddress((void**)&pwwhi, g_wwhi);
    cudaGetSymbolAddress((void**)&pwwlo, g_wwlo);
    cudaGetSymbolAddress((void**)&pskhi, g_skhi);
    cudaGetSymbolAddress((void**)&psklo, g_sklo);
    cudaGetSymbolAddress((void**)&ppjhi, g_pjhi);
    cudaGetSymbolAddress((void**)&ppjlo, g_pjlo);
    cudaGetSymbolAddress((void**)&pathi, g_athi);
    cudaGetSymbolAddress((void**)&patlo, g_atlo);

    cudaFuncSetAttribute(gemm_hmma_kernel,
                         cudaFuncAttributeMaxDynamicSharedMemorySize, GEMM_SMEM);
    cudaFuncSetAttribute(gemm_hmma64_kernel,
                         cudaFuncAttributeMaxDynamicSharedMemorySize, GEMM_SMEM64);

    // operand prep (one launch) + group lists (also zeroes s1/s2)
    fused_prep_kernel<<<1536 + 3 * WQ / 256, 256>>>(eh, er, et, W_w, skip_w, proj_w);
    build_groups_kernel<<<1, 1024>>>(h_id);

    // GEMM 1 (dual): Wh = e @ W_w^T (+ fused s1/s2) ; skip = e @ skip_w^T + skip_b
    gemm_hmma_kernel<<<dim3(16, 16), 256, GEMM_SMEM>>>(
        pehi, pelo,
        pwwhi, pwwlo, pWh, nullptr, nullptr,
        pskhi, psklo, pskip, skip_b, 8, a);

    // grouped attention -> bf16 hi/lo (4-row tiles, two-phase smem wg)
    attn_kernel<<<dim3(32, 16), 256>>>();

    // GEMM 2: out = att @ proj_w^T + proj_b + skip (64x96 tiles, full wave)
    gemm_hmma64_kernel<<<dim3(8, 32), 256, GEMM_SMEM64>>>(
        pathi, patlo, ppjhi, ppjlo, out, proj_b, pskip);
}